// round 7
// baseline (speedup 1.0000x reference)
#include <cuda_runtime.h>
#include <cstdint>

#define T_STEPS 128
#define CIN 16
#define H 64
#define W 64
#define CO 64
#define PLANE (H*W)            // 4096
#define FRAME (CO*PLANE)       // 262144
#define TOTAL (T_STEPS*FRAME)  // 33554432
#define K9 (CIN*9)             // 144

// conv scratch + weight staging (static __device__: allocation-free)
__device__ float g_conv[TOTAL];
__device__ float g_wt[K9 * CO];          // transposed weights staging

// weights in constant memory: cW[k9*64 + co]  (co fastest, pairs contiguous)
__constant__ float cW[K9 * CO];          // 36 KB

#define TILE_H 8
#define XS_H   (TILE_H + 2)    // 10
#define XS_WD  (W + 2)         // 66 values per row
#define XS_STRIDE 67           // pad to odd stride
#define CO_PER_BLK 16

// ---- packed f32x2 helpers (sm_103a FFMA2 path; only reachable via PTX) ----
__device__ __forceinline__ uint64_t pk2(float lo, float hi) {
    uint64_t r;
    asm("mov.b64 %0, {%1, %2};" : "=l"(r) : "f"(lo), "f"(hi));
    return r;
}
__device__ __forceinline__ void upk2(uint64_t v, float& lo, float& hi) {
    asm("mov.b64 {%0, %1}, %2;" : "=f"(lo), "=f"(hi) : "l"(v));
}
__device__ __forceinline__ uint64_t fma2(uint64_t a, uint64_t b, uint64_t c) {
    uint64_t r;
    asm("fma.rn.f32x2 %0, %1, %2, %3;" : "=l"(r) : "l"(a), "l"(b), "l"(c));
    return r;
}

// ---------------------------------------------------------------------------
// Weight transpose: g_wt[k9*64 + co] = Wt[co*144 + k9]
// ---------------------------------------------------------------------------
__global__ void transpose_w(const float* __restrict__ Wt) {
    int i = blockIdx.x * 256 + threadIdx.x;
    if (i < K9 * CO) {
        int co = i & 63;
        int k9 = i >> 6;
        g_wt[i] = Wt[co * K9 + k9];
    }
}

// ---------------------------------------------------------------------------
// Conv kernel: grid (8 h-tiles, 4 co-groups, 128 t), 128 threads.
// Tile = 8h x 64w (full width). Thread computes ALL 16 c_out of its co-group
// for 4 w at one h; c_out packed in PAIRS (f32x2 acc, 32 u64 accs).
// Weight index depends ONLY on blockIdx.y + loop constants -> provably
// uniform __constant__ address -> LDCU -> UR operand -> FFMA2 GPR-bank rt=2.
// x: scalar floats in smem, packed (v,v) via MOV (ALU pipe, overlaps FMA).
// ---------------------------------------------------------------------------
__global__ __launch_bounds__(128, 4)
void conv_kernel(const float* __restrict__ x, const float* __restrict__ b) {
    __shared__ float xs[CIN * XS_H * XS_STRIDE];   // 10720 f = 42.9 KB

    const int tid = threadIdx.x;
    const int t   = blockIdx.z;
    const int cog = blockIdx.y;                    // co group (16 each)
    const int h0  = blockIdx.x * TILE_H;
    const int co0 = cog * CO_PER_BLK;              // uniform (blockIdx-derived)

    // Load x halo tile (10 rows x 66 cols x 16 cin) with zero padding
    const float* xt = x + (size_t)t * (CIN * PLANE);
    #pragma unroll 4
    for (int i = tid; i < CIN * XS_H * XS_WD; i += 128) {
        int c   = i % XS_WD;               // 0..65 -> global w = c-1
        int rc  = i / XS_WD;
        int r   = rc % XS_H;               // 0..9  -> global y = h0-1+r
        int cin = rc / XS_H;
        int y   = h0 - 1 + r;
        int wg  = c - 1;
        float v = 0.0f;
        if ((unsigned)y < (unsigned)H && (unsigned)wg < (unsigned)W)
            v = xt[cin * PLANE + y * W + wg];
        xs[cin * (XS_H * XS_STRIDE) + r * XS_STRIDE + c] = v;
    }
    __syncthreads();

    const int hl = tid >> 4;               // 0..7
    const int wl = (tid & 15) * 4;         // 0,4,...,60

    // acc[p][w] packs c_out pair (2p, 2p+1) of this co-group at column w
    uint64_t acc[8][4];
    #pragma unroll
    for (int p = 0; p < 8; p++) {
        uint64_t bp = pk2(b[co0 + 2 * p], b[co0 + 2 * p + 1]);
        #pragma unroll
        for (int w = 0; w < 4; w++) acc[p][w] = bp;
    }

    #pragma unroll 4
    for (int cin = 0; cin < CIN; cin++) {
        #pragma unroll
        for (int kh = 0; kh < 3; kh++) {
            // output w = wl+ww taps smem cols (wl+ww)..(wl+ww+2)
            const float* row =
                &xs[cin * (XS_H * XS_STRIDE) + (hl + kh) * XS_STRIDE + wl];
            uint64_t xx[6];
            #pragma unroll
            for (int j = 0; j < 6; j++) {
                float xv = row[j];
                xx[j] = pk2(xv, xv);
            }
            // uniform constant addresses -> LDCU.64 (UR pairs)
            const float* wbase = &cW[(cin * 9 + kh * 3) * CO + co0];
            #pragma unroll
            for (int p = 0; p < 8; p++) {
                uint64_t wk0 = *(const uint64_t*)(wbase + 2 * p);
                uint64_t wk1 = *(const uint64_t*)(wbase + CO + 2 * p);
                uint64_t wk2 = *(const uint64_t*)(wbase + 2 * CO + 2 * p);
                #pragma unroll
                for (int w = 0; w < 4; w++) {
                    acc[p][w] = fma2(xx[w],     wk0, acc[p][w]);
                    acc[p][w] = fma2(xx[w + 1], wk1, acc[p][w]);
                    acc[p][w] = fma2(xx[w + 2], wk2, acc[p][w]);
                }
            }
        }
    }

    // Unpack and store: one float4 per c_out (w-contiguous, 16B aligned)
    #pragma unroll
    for (int p = 0; p < 8; p++) {
        float lo[4], hi[4];
        #pragma unroll
        for (int w = 0; w < 4; w++) upk2(acc[p][w], lo[w], hi[w]);
        int co_e = co0 + 2 * p;
        size_t base = (size_t)t * FRAME + (h0 + hl) * W + wl;
        *(float4*)&g_conv[base + (size_t)co_e * PLANE] =
            make_float4(lo[0], lo[1], lo[2], lo[3]);
        *(float4*)&g_conv[base + (size_t)(co_e + 1) * PLANE] =
            make_float4(hi[0], hi[1], hi[2], hi[3]);
    }
}

// ---------------------------------------------------------------------------
// Scan kernel: one thread per (c_out,h,w); sequential LIF over T.
// Proven 38.6us / 70% DRAM at 256 threads, scalar loads (R3/R4 version).
// ---------------------------------------------------------------------------
__global__ __launch_bounds__(256)
void scan_kernel(float* __restrict__ out) {
    const int idx = blockIdx.x * 256 + threadIdx.x;   // < FRAME
    const float* cp = g_conv + idx;
    float* op = out + idx;
    float state = 0.0f;
    #pragma unroll 8
    for (int t = 0; t < T_STEPS; t++) {
        float v = cp[(size_t)t * FRAME];
        state += v;
        float spike = (state >= 8.0f) ? 1.0f : 0.0f;      // fire
        state = (state >= 8.0f) ? 0.0f : state;           // reset-to-value 0
        state = (state > -1.0f) ? state : -1.0f;          // Threshold(-1,-1)
        op[(size_t)t * FRAME] = spike;
    }
}

extern "C" void kernel_launch(void* const* d_in, const int* in_sizes, int n_in,
                              void* d_out, int out_size) {
    // Identify inputs by unique element counts (robust to ordering)
    const float* x  = nullptr;
    const float* Wt = nullptr;
    const float* b  = nullptr;
    for (int i = 0; i < n_in; i++) {
        if (in_sizes[i] == T_STEPS * CIN * PLANE) x  = (const float*)d_in[i];
        else if (in_sizes[i] == CO * CIN * 9)     Wt = (const float*)d_in[i];
        else if (in_sizes[i] == CO)               b  = (const float*)d_in[i];
    }
    float* out = (float*)d_out;

    // 1) transpose weights into staging, 2) D2D copy into __constant__ cW
    transpose_w<<<(K9 * CO + 255) / 256, 256>>>(Wt);
    void* wt_ptr = nullptr;
    cudaGetSymbolAddress(&wt_ptr, g_wt);
    cudaMemcpyToSymbolAsync(cW, wt_ptr, K9 * CO * sizeof(float), 0,
                            cudaMemcpyDeviceToDevice, 0);

    dim3 grid(H / TILE_H, CO / CO_PER_BLK, T_STEPS);   // 8 x 4 x 128 = 4096
    conv_kernel<<<grid, 128>>>(x, b);
    scan_kernel<<<FRAME / 256, 256>>>(out);
}